// round 1
// baseline (speedup 1.0000x reference)
#include <cuda_runtime.h>
#include <cstdint>
#include <cstddef>

// ---------------- problem constants ----------------
#define T_LEN   16384
#define B_SZ    8
#define NTOT    (T_LEN * B_SZ)     // 131072 = 2^17
#define RESC    120
#define SKIPC   240
#define NQ      256
#define NBLK    16

// ---------------- device scratch (no allocs allowed) ----------------
__device__ __align__(16) float g_X [RESC  * NTOT];   // residual activations
__device__ __align__(16) float g_Z [RESC  * NTOT];   // gated activations
__device__ __align__(16) float g_SK[SKIPC * NTOT];   // skip accumulator
__device__ __align__(16) float g_H [NQ    * NTOT];   // hidden after head1

// packed weights: layout [K][Mpad], zero-padded
__device__ __align__(16) float g_Wfg[NBLK * 240 * 256]; // K=240 (tap0|tap1), M=256 (f/g interleaved pairs)
__device__ __align__(16) float g_Bfg[NBLK * 256];
__device__ __align__(16) float g_Wrs[NBLK * 120 * 384]; // K=120, M: [0,128)=res, [128,368)=skip
__device__ __align__(16) float g_Brs[NBLK * 384];
__device__ __align__(16) float g_W1p[240 * 256];        // K=240, M=256
__device__ __align__(16) float g_W2p[256 * 256];        // K=256, M=256

// ---------------- f32x2 helpers ----------------
#define PACK2(d, s)  asm("mov.b64 %0, {%1, %1};" : "=l"(d) : "r"(__float_as_uint(s)))
#define FMA2(acc, a, b) asm("fma.rn.f32x2 %0, %1, %2, %0;" : "+l"(acc) : "l"(a), "l"(b))
#define UNPACK2(lo, hi, v) do { unsigned int _u0, _u1; \
    asm("mov.b64 {%0, %1}, %2;" : "=r"(_u0), "=r"(_u1) : "l"(v)); \
    lo = __uint_as_float(_u0); hi = __uint_as_float(_u1); } while (0)

__device__ __forceinline__ float safe_tanh(float x) {
    float ax = fabsf(x);
    float e  = __expf(-2.0f * ax);
    float t  = (1.0f - e) / (1.0f + e);
    return copysignf(t, x);
}
__device__ __forceinline__ float sigmoidf_(float x) {
    return 1.0f / (1.0f + __expf(-x));
}

// ---------------- packing kernels ----------------
__global__ void pack_fg_kernel(const float* __restrict__ Wf, const float* __restrict__ bf,
                               const float* __restrict__ Wg, const float* __restrict__ bg) {
    int idx = blockIdx.x * blockDim.x + threadIdx.x;
    const int total = NBLK * 240 * 256;
    if (idx < total) {
        int m = idx & 255;
        int k = (idx >> 8) % 240;
        int i = idx / (240 * 256);
        int c = m >> 1, isg = m & 1;
        float v = 0.0f;
        if (c < RESC) {
            int kc = k % RESC, tap = k / RESC;   // tap0 -> x[t-d], tap1 -> x[t]
            const float* src = isg ? Wg : Wf;    // [i][c][kc][tap]
            v = src[(((size_t)i * RESC + c) * RESC + kc) * 2 + tap];
        }
        g_Wfg[idx] = v;
    }
    if (idx < NBLK * 256) {
        int m = idx & 255; int i = idx >> 8;
        int c = m >> 1, isg = m & 1;
        g_Bfg[idx] = (c < RESC) ? (isg ? bg[i * RESC + c] : bf[i * RESC + c]) : 0.0f;
    }
}

__global__ void pack_rs_kernel(const float* __restrict__ Wres, const float* __restrict__ bres,
                               const float* __restrict__ Wskip, const float* __restrict__ bskip) {
    int idx = blockIdx.x * blockDim.x + threadIdx.x;
    const int total = NBLK * 120 * 384;
    if (idx < total) {
        int m = idx % 384;
        int k = (idx / 384) % 120;
        int i = idx / (384 * 120);
        float v = 0.0f;
        if (m < 128) {
            if (m < RESC) v = Wres[((size_t)i * RESC + m) * RESC + k];
        } else {
            int c = m - 128;
            if (c < SKIPC) v = Wskip[((size_t)i * SKIPC + c) * RESC + k];
        }
        g_Wrs[idx] = v;
    }
    if (idx < NBLK * 384) {
        int m = idx % 384; int i = idx / 384;
        float v = 0.0f;
        if (m < 128) { if (m < RESC) v = bres[i * RESC + m]; }
        else { int c = m - 128; if (c < SKIPC) v = bskip[i * SKIPC + c]; }
        g_Brs[idx] = v;
    }
}

__global__ void pack_heads_kernel(const float* __restrict__ W1, const float* __restrict__ W2) {
    int idx = blockIdx.x * blockDim.x + threadIdx.x;
    if (idx < 240 * 256) {       // [k][m] <- W1[m][k]
        int m = idx & 255; int k = idx >> 8;
        g_W1p[idx] = W1[(size_t)m * 240 + k];
    }
    if (idx < 256 * 256) {
        int m = idx & 255; int k = idx >> 8;
        g_W2p[idx] = W2[(size_t)m * 256 + k];
    }
}

// input 1x1 conv + skip zero init
__global__ void init_kernel(const float* __restrict__ wave,
                            const float* __restrict__ W_in,
                            const float* __restrict__ b_in) {
    int idx = blockIdx.x * blockDim.x + threadIdx.x;   // over 360*NTOT
    int r = idx >> 17;              // / NTOT
    int n = idx & (NTOT - 1);
    if (r < RESC) g_X[(size_t)r * NTOT + n] = W_in[r] * wave[n] + b_in[r];
    else          g_SK[(size_t)(r - RESC) * NTOT + n] = 0.0f;
}

// ---------------- fused GEMM ----------------
// OUT_MODE: 0=FG (z=tanh*sig -> g_Z), 1=RS (+= g_X / g_SK), 2=H1 (relu -> g_H), 3=logits (-> dout)
// IN_MODE : 0=XCAT(shifted|plain from g_X), 1=plain, 2=relu
template<int K, int BK, int IN_MODE, int OUT_MODE, int MP>
__global__ void __launch_bounds__(256) gemm_kernel(int blk, int d,
                                                   const float* __restrict__ bias_ext,
                                                   float* __restrict__ dout) {
    __shared__ float Ws[BK][128];
    __shared__ float Xs[BK][64];

    const int tid = threadIdx.x;
    const int tm = tid >> 4;          // 0..15, 8 rows each
    const int tn = tid & 15;          // 0..15, 4 cols each
    const int n0 = blockIdx.x * 64;
    const int mbase = blockIdx.y * 128;

    const float* W; const float* bias; const float* Xin;
    if (OUT_MODE == 0)      { W = g_Wfg + (size_t)blk * 240 * 256; bias = g_Bfg + blk * 256; Xin = g_X; }
    else if (OUT_MODE == 1) { W = g_Wrs + (size_t)blk * 120 * 384; bias = g_Brs + blk * 384; Xin = g_Z; }
    else if (OUT_MODE == 2) { W = g_W1p; bias = bias_ext; Xin = g_SK; }
    else                    { W = g_W2p; bias = bias_ext; Xin = g_H; }

    unsigned long long acc[4][4];
#pragma unroll
    for (int p = 0; p < 4; p++)
#pragma unroll
        for (int j = 0; j < 4; j++) acc[p][j] = 0ull;

    for (int kc = 0; kc < K; kc += BK) {
        // ---- stage W tile: BK x 128 ----
#pragma unroll
        for (int i = 0; i < (BK * 128 / 4) / 256; i++) {
            int e4 = tid + i * 256;
            int kr = e4 >> 5, m4 = e4 & 31;
            *(float4*)&Ws[kr][m4 * 4] =
                *(const float4*)(W + (size_t)(kc + kr) * MP + mbase + m4 * 4);
        }
        // ---- stage X tile: BK x 64 ----
#pragma unroll
        for (int i = 0; i < (BK * 64) / 256; i++) {
            int e = tid + i * 256;
            int kr = e >> 6, nl = e & 63;
            int n = n0 + nl;
            int kk = kc + kr;
            float v;
            if (IN_MODE == 0) {
                if (kk < RESC) {
                    int t = n & (T_LEN - 1);
                    v = (t >= d) ? Xin[(size_t)kk * NTOT + (n - d)] : 0.0f;
                } else {
                    v = Xin[(size_t)(kk - RESC) * NTOT + n];
                }
            } else if (IN_MODE == 1) {
                v = Xin[(size_t)kk * NTOT + n];
            } else {
                v = fmaxf(Xin[(size_t)kk * NTOT + n], 0.0f);
            }
            Xs[kr][nl] = v;
        }
        __syncthreads();

#pragma unroll
        for (int k = 0; k < BK; k++) {
            ulonglong2 wa = *(const ulonglong2*)&Ws[k][tm * 8];
            ulonglong2 wb = *(const ulonglong2*)&Ws[k][tm * 8 + 4];
            float4 xv = *(const float4*)&Xs[k][tn * 4];
            unsigned long long x0, x1, x2, x3;
            PACK2(x0, xv.x); PACK2(x1, xv.y); PACK2(x2, xv.z); PACK2(x3, xv.w);
            FMA2(acc[0][0], wa.x, x0); FMA2(acc[0][1], wa.x, x1);
            FMA2(acc[0][2], wa.x, x2); FMA2(acc[0][3], wa.x, x3);
            FMA2(acc[1][0], wa.y, x0); FMA2(acc[1][1], wa.y, x1);
            FMA2(acc[1][2], wa.y, x2); FMA2(acc[1][3], wa.y, x3);
            FMA2(acc[2][0], wb.x, x0); FMA2(acc[2][1], wb.x, x1);
            FMA2(acc[2][2], wb.x, x2); FMA2(acc[2][3], wb.x, x3);
            FMA2(acc[3][0], wb.y, x0); FMA2(acc[3][1], wb.y, x1);
            FMA2(acc[3][2], wb.y, x2); FMA2(acc[3][3], wb.y, x3);
        }
        __syncthreads();
    }

    const int ncol = n0 + tn * 4;

    if (OUT_MODE == 0) {
        // rows are (f,g) interleaved pairs -> z = tanh(f)*sigmoid(g)
#pragma unroll
        for (int p = 0; p < 4; p++) {
            int m = mbase + tm * 8 + 2 * p;
            int c = m >> 1;
            if (c < RESC) {
                float bfv = bias[m], bgv = bias[m + 1];
                float4 zv;
                float f, g;
                UNPACK2(f, g, acc[p][0]); zv.x = safe_tanh(f + bfv) * sigmoidf_(g + bgv);
                UNPACK2(f, g, acc[p][1]); zv.y = safe_tanh(f + bfv) * sigmoidf_(g + bgv);
                UNPACK2(f, g, acc[p][2]); zv.z = safe_tanh(f + bfv) * sigmoidf_(g + bgv);
                UNPACK2(f, g, acc[p][3]); zv.w = safe_tanh(f + bfv) * sigmoidf_(g + bgv);
                *(float4*)&g_Z[(size_t)c * NTOT + ncol] = zv;
            }
        }
    } else {
#pragma unroll
        for (int p = 0; p < 4; p++) {
            float lo0, hi0, lo1, hi1, lo2, hi2, lo3, hi3;
            UNPACK2(lo0, hi0, acc[p][0]);
            UNPACK2(lo1, hi1, acc[p][1]);
            UNPACK2(lo2, hi2, acc[p][2]);
            UNPACK2(lo3, hi3, acc[p][3]);
            int m0 = mbase + tm * 8 + 2 * p;
#pragma unroll
            for (int r = 0; r < 2; r++) {
                int mm = m0 + r;
                float v0 = r ? hi0 : lo0, v1 = r ? hi1 : lo1;
                float v2 = r ? hi2 : lo2, v3 = r ? hi3 : lo3;
                if (OUT_MODE == 1) {
                    float bv = bias[mm];
                    if (mbase == 0) {
                        if (mm < RESC) {
                            float4 cur = *(const float4*)&g_X[(size_t)mm * NTOT + ncol];
                            cur.x += v0 + bv; cur.y += v1 + bv;
                            cur.z += v2 + bv; cur.w += v3 + bv;
                            *(float4*)&g_X[(size_t)mm * NTOT + ncol] = cur;
                        }
                    } else {
                        int c = mm - 128;
                        if (c < SKIPC) {
                            float4 cur = *(const float4*)&g_SK[(size_t)c * NTOT + ncol];
                            cur.x += v0 + bv; cur.y += v1 + bv;
                            cur.z += v2 + bv; cur.w += v3 + bv;
                            *(float4*)&g_SK[(size_t)c * NTOT + ncol] = cur;
                        }
                    }
                } else if (OUT_MODE == 2) {
                    float bv = bias[mm];
                    float4 o;
                    o.x = fmaxf(v0 + bv, 0.0f); o.y = fmaxf(v1 + bv, 0.0f);
                    o.z = fmaxf(v2 + bv, 0.0f); o.w = fmaxf(v3 + bv, 0.0f);
                    *(float4*)&g_H[(size_t)mm * NTOT + ncol] = o;
                } else { // logits
                    float bv = bias[mm];
                    int b = n0 >> 14;                       // / T_LEN
                    int t0 = (ncol & (T_LEN - 1));
                    float4 o;
                    o.x = v0 + bv; o.y = v1 + bv; o.z = v2 + bv; o.w = v3 + bv;
                    *(float4*)&dout[((size_t)b * NQ + mm) * T_LEN + t0] = o;
                }
            }
        }
    }
}

// ---------------- launch ----------------
extern "C" void kernel_launch(void* const* d_in, const int* in_sizes, int n_in,
                              void* d_out, int out_size) {
    const float* wave  = (const float*)d_in[0];
    const float* W_in  = (const float*)d_in[1];
    const float* b_in  = (const float*)d_in[2];
    const float* Wf    = (const float*)d_in[3];
    const float* bf    = (const float*)d_in[4];
    const float* Wg    = (const float*)d_in[5];
    const float* bg    = (const float*)d_in[6];
    const float* Wres  = (const float*)d_in[7];
    const float* bres  = (const float*)d_in[8];
    const float* Wskip = (const float*)d_in[9];
    const float* bskip = (const float*)d_in[10];
    const float* W1    = (const float*)d_in[11];
    const float* b1    = (const float*)d_in[12];
    const float* W2    = (const float*)d_in[13];
    const float* b2    = (const float*)d_in[14];
    float* out = (float*)d_out;

    pack_fg_kernel<<<(NBLK * 240 * 256 + 255) / 256, 256>>>(Wf, bf, Wg, bg);
    pack_rs_kernel<<<(NBLK * 120 * 384 + 255) / 256, 256>>>(Wres, bres, Wskip, bskip);
    pack_heads_kernel<<<(256 * 256 + 255) / 256, 256>>>(W1, W2);
    init_kernel<<<(360 * NTOT) / 256, 256>>>(wave, W_in, b_in);

    static const int dil[NBLK] = {1, 2, 4, 8, 16, 32, 64, 128,
                                  1, 2, 4, 8, 16, 32, 64, 128};

    dim3 gFG(NTOT / 64, 2);
    dim3 gRS(NTOT / 64, 3);
    dim3 gH (NTOT / 64, 2);

    for (int i = 0; i < NBLK; i++) {
        gemm_kernel<240, 24, 0, 0, 256><<<gFG, 256>>>(i, dil[i], nullptr, nullptr);
        gemm_kernel<120, 24, 1, 1, 384><<<gRS, 256>>>(i, 0, nullptr, nullptr);
    }
    gemm_kernel<240, 24, 2, 2, 256><<<gH, 256>>>(0, 0, b1, nullptr);
    gemm_kernel<256, 32, 1, 3, 256><<<gH, 256>>>(0, 0, b2, out);
}

// round 2
// speedup vs baseline: 1.1439x; 1.1439x over previous
#include <cuda_runtime.h>
#include <cstdint>
#include <cstddef>

// ---------------- problem constants ----------------
#define T_LEN   16384
#define B_SZ    8
#define NTOT    (T_LEN * B_SZ)     // 131072 = 2^17
#define RESC    120
#define SKIPC   240
#define NQ      256
#define NBLK    16

// ---------------- device scratch ----------------
__device__ __align__(16) float g_X [RESC  * NTOT];
__device__ __align__(16) float g_Z [RESC  * NTOT];
__device__ __align__(16) float g_SK[SKIPC * NTOT];
__device__ __align__(16) float g_H [NQ    * NTOT];

// packed weights: layout [K][Mpad], zero-padded
__device__ __align__(16) float g_Wfg[NBLK * 240 * 256]; // K=240 (tap0|tap1), M=256 (f/g pairs)
__device__ __align__(16) float g_Bfg[NBLK * 256];
__device__ __align__(16) float g_Wrs[NBLK * 128 * 384]; // K padded to 128, M: [0,128)=res, [128,368)=skip
__device__ __align__(16) float g_Brs[NBLK * 384];
__device__ __align__(16) float g_W1p[240 * 256];
__device__ __align__(16) float g_W2p[256 * 256];

// ---------------- f32x2 helpers ----------------
#define PACK2(d, s)  asm("mov.b64 %0, {%1, %1};" : "=l"(d) : "r"(__float_as_uint(s)))
#define FMA2(acc, a, b) asm("fma.rn.f32x2 %0, %1, %2, %0;" : "+l"(acc) : "l"(a), "l"(b))
#define UNPACK2(lo, hi, v) do { unsigned int _u0, _u1; \
    asm("mov.b64 {%0, %1}, %2;" : "=r"(_u0), "=r"(_u1) : "l"(v)); \
    lo = __uint_as_float(_u0); hi = __uint_as_float(_u1); } while (0)

__device__ __forceinline__ float safe_tanh(float x) {
    float ax = fabsf(x);
    float e  = __expf(-2.0f * ax);
    float t  = (1.0f - e) / (1.0f + e);
    return copysignf(t, x);
}
__device__ __forceinline__ float sigmoidf_(float x) {
    return 1.0f / (1.0f + __expf(-x));
}

// ---------------- packing kernels ----------------
__global__ void pack_fg_kernel(const float* __restrict__ Wf, const float* __restrict__ bf,
                               const float* __restrict__ Wg, const float* __restrict__ bg) {
    int idx = blockIdx.x * blockDim.x + threadIdx.x;
    const int total = NBLK * 240 * 256;
    if (idx < total) {
        int m = idx & 255;
        int k = (idx >> 8) % 240;
        int i = idx / (240 * 256);
        int c = m >> 1, isg = m & 1;
        float v = 0.0f;
        if (c < RESC) {
            int kc = k % RESC, tap = k / RESC;   // tap0 -> x[t-d], tap1 -> x[t]
            const float* src = isg ? Wg : Wf;
            v = src[(((size_t)i * RESC + c) * RESC + kc) * 2 + tap];
        }
        g_Wfg[idx] = v;
    }
    if (idx < NBLK * 256) {
        int m = idx & 255; int i = idx >> 8;
        int c = m >> 1, isg = m & 1;
        g_Bfg[idx] = (c < RESC) ? (isg ? bg[i * RESC + c] : bf[i * RESC + c]) : 0.0f;
    }
}

__global__ void pack_rs_kernel(const float* __restrict__ Wres, const float* __restrict__ bres,
                               const float* __restrict__ Wskip, const float* __restrict__ bskip) {
    int idx = blockIdx.x * blockDim.x + threadIdx.x;
    const int total = NBLK * 128 * 384;
    if (idx < total) {
        int m = idx % 384;
        int k = (idx / 384) & 127;
        int i = idx / (384 * 128);
        float v = 0.0f;
        if (k < RESC) {
            if (m < 128) {
                if (m < RESC) v = Wres[((size_t)i * RESC + m) * RESC + k];
            } else {
                int c = m - 128;
                if (c < SKIPC) v = Wskip[((size_t)i * SKIPC + c) * RESC + k];
            }
        }
        g_Wrs[idx] = v;
    }
    if (idx < NBLK * 384) {
        int m = idx % 384; int i = idx / 384;
        float v = 0.0f;
        if (m < 128) { if (m < RESC) v = bres[i * RESC + m]; }
        else { int c = m - 128; if (c < SKIPC) v = bskip[i * SKIPC + c]; }
        g_Brs[idx] = v;
    }
}

__global__ void pack_heads_kernel(const float* __restrict__ W1, const float* __restrict__ W2) {
    int idx = blockIdx.x * blockDim.x + threadIdx.x;
    if (idx < 240 * 256) {
        int m = idx & 255; int k = idx >> 8;
        g_W1p[idx] = W1[(size_t)m * 240 + k];
    }
    if (idx < 256 * 256) {
        int m = idx & 255; int k = idx >> 8;
        g_W2p[idx] = W2[(size_t)m * 256 + k];
    }
}

__global__ void init_kernel(const float* __restrict__ wave,
                            const float* __restrict__ W_in,
                            const float* __restrict__ b_in) {
    int idx = blockIdx.x * blockDim.x + threadIdx.x;
    int r = idx >> 17;
    int n = idx & (NTOT - 1);
    if (r < RESC) g_X[(size_t)r * NTOT + n] = W_in[r] * wave[n] + b_in[r];
    else          g_SK[(size_t)(r - RESC) * NTOT + n] = 0.0f;
}

// ---------------- fused GEMM: CTA tile 128x128, thread tile 8x8 ----------------
// IN_MODE : 0 = dilated concat from g_X, 1 = plain (row-guard KV), 2 = relu from g_SK
// OUT_MODE: 0 = FG (z=tanh*sig -> g_Z), 1 = RS (+= g_X / g_SK), 2 = relu -> g_H, 3 = logits
template<int K, int KV, int IN_MODE, int OUT_MODE, int MP, int DALIGN>
__global__ void __launch_bounds__(256, 2) gemm_kernel(int blk, int d,
                                                      const float* __restrict__ bias_ext,
                                                      float* __restrict__ dout) {
    __shared__ float Ws[16][128];
    __shared__ float Xs[16][128];

    const int tid = threadIdx.x;
    const int w = tid >> 5, l = tid & 31;
    const int my = (w >> 1) * 4 + (l >> 3);   // 0..15, row group (8 rows)
    const int nx = (w & 1) * 8 + (l & 7);     // 0..15, col group (8 cols)
    const int n0 = blockIdx.x * 128;
    const int mbase = blockIdx.y * 128;

    const float* W; const float* bias; const float* Xin;
    if (OUT_MODE == 0)      { W = g_Wfg + (size_t)blk * 240 * 256; bias = g_Bfg + blk * 256; Xin = g_X; }
    else if (OUT_MODE == 1) { W = g_Wrs + (size_t)blk * 128 * 384; bias = g_Brs + blk * 384; Xin = g_Z; }
    else if (OUT_MODE == 2) { W = g_W1p; bias = bias_ext; Xin = g_SK; }
    else                    { W = g_W2p; bias = bias_ext; Xin = g_H; }

    const bool first_tile = ((n0 & (T_LEN - 1)) == 0);

    unsigned long long acc[8][4];
#pragma unroll
    for (int r = 0; r < 8; r++)
#pragma unroll
        for (int c = 0; c < 4; c++) acc[r][c] = 0ull;

    for (int kc = 0; kc < K; kc += 16) {
        // ---- stage W tile: 16 x 128 (float4, fully coalesced) ----
#pragma unroll
        for (int i = 0; i < 2; i++) {
            int e4 = tid + i * 256;
            int kr = e4 >> 5, m4 = e4 & 31;
            ((float4*)Ws)[e4] = *(const float4*)(W + (size_t)(kc + kr) * MP + mbase + m4 * 4);
        }
        // ---- stage X tile: 16 x 128 ----
#pragma unroll
        for (int i = 0; i < 2; i++) {
            int e4 = tid + i * 256;
            int kr = e4 >> 5, nl4 = e4 & 31;
            int kk = kc + kr;
            int n = n0 + nl4 * 4;
            float4 v;
            if (IN_MODE == 0) {
                if (kk < RESC) {
                    // shifted tap: x[t - d]
                    const float* src = Xin + (size_t)kk * NTOT + n - d;
                    if (first_tile) {
                        int t = nl4 * 4;
                        v.x = (t + 0 >= d) ? src[0] : 0.0f;
                        v.y = (t + 1 >= d) ? src[1] : 0.0f;
                        v.z = (t + 2 >= d) ? src[2] : 0.0f;
                        v.w = (t + 3 >= d) ? src[3] : 0.0f;
                    } else if (DALIGN == 4) {
                        v = *(const float4*)src;
                    } else if (DALIGN == 2) {
                        float2 a = *(const float2*)src;
                        float2 b = *(const float2*)(src + 2);
                        v.x = a.x; v.y = a.y; v.z = b.x; v.w = b.y;
                    } else {
                        v.x = src[0]; v.y = src[1]; v.z = src[2]; v.w = src[3];
                    }
                } else {
                    v = *(const float4*)(Xin + (size_t)(kk - RESC) * NTOT + n);
                }
            } else if (IN_MODE == 1) {
                if (kk < KV) v = *(const float4*)(Xin + (size_t)kk * NTOT + n);
                else { v.x = v.y = v.z = v.w = 0.0f; }
            } else {
                float4 s = *(const float4*)(Xin + (size_t)kk * NTOT + n);
                v.x = fmaxf(s.x, 0.0f); v.y = fmaxf(s.y, 0.0f);
                v.z = fmaxf(s.z, 0.0f); v.w = fmaxf(s.w, 0.0f);
            }
            ((float4*)Xs)[e4] = v;
        }
        __syncthreads();

#pragma unroll
        for (int k = 0; k < 16; k++) {
            float4 wv0 = *(const float4*)&Ws[k][my * 8];
            float4 wv1 = *(const float4*)&Ws[k][my * 8 + 4];
            unsigned long long wd[8];
            PACK2(wd[0], wv0.x); PACK2(wd[1], wv0.y);
            PACK2(wd[2], wv0.z); PACK2(wd[3], wv0.w);
            PACK2(wd[4], wv1.x); PACK2(wd[5], wv1.y);
            PACK2(wd[6], wv1.z); PACK2(wd[7], wv1.w);
            ulonglong2 xa = *(const ulonglong2*)&Xs[k][nx * 8];
            ulonglong2 xb = *(const ulonglong2*)&Xs[k][nx * 8 + 4];
#pragma unroll
            for (int r = 0; r < 8; r++) {
                FMA2(acc[r][0], wd[r], xa.x);
                FMA2(acc[r][1], wd[r], xa.y);
                FMA2(acc[r][2], wd[r], xb.x);
                FMA2(acc[r][3], wd[r], xb.y);
            }
        }
        __syncthreads();
    }

    const int ncolb = n0 + nx * 8;

    if (OUT_MODE == 0) {
        // rows are (f,g) interleaved pairs
#pragma unroll
        for (int p = 0; p < 4; p++) {
            int m = mbase + my * 8 + 2 * p;
            int c = m >> 1;
            if (c < RESC) {
                float bfv = bias[m], bgv = bias[m + 1];
#pragma unroll
                for (int cp = 0; cp < 4; cp++) {
                    float flo, fhi, glo, ghi;
                    UNPACK2(flo, fhi, acc[2 * p][cp]);
                    UNPACK2(glo, ghi, acc[2 * p + 1][cp]);
                    float2 z;
                    z.x = safe_tanh(flo + bfv) * sigmoidf_(glo + bgv);
                    z.y = safe_tanh(fhi + bfv) * sigmoidf_(ghi + bgv);
                    *(float2*)&g_Z[(size_t)c * NTOT + ncolb + cp * 2] = z;
                }
            }
        }
    } else if (OUT_MODE == 1) {
#pragma unroll
        for (int r = 0; r < 8; r++) {
            int m = mbase + my * 8 + r;
            float* tgt = nullptr;
            if (mbase == 0) { if (m < RESC) tgt = &g_X[(size_t)m * NTOT + ncolb]; }
            else { int c = m - 128; if (c < SKIPC) tgt = &g_SK[(size_t)c * NTOT + ncolb]; }
            if (tgt) {
                float bv = bias[m];
#pragma unroll
                for (int cp = 0; cp < 4; cp++) {
                    float lo, hi;
                    UNPACK2(lo, hi, acc[r][cp]);
                    float2 cur = *(float2*)(tgt + cp * 2);
                    cur.x += lo + bv; cur.y += hi + bv;
                    *(float2*)(tgt + cp * 2) = cur;
                }
            }
        }
    } else if (OUT_MODE == 2) {
#pragma unroll
        for (int r = 0; r < 8; r++) {
            int m = mbase + my * 8 + r;
            float bv = bias[m];
#pragma unroll
            for (int cp = 0; cp < 4; cp++) {
                float lo, hi;
                UNPACK2(lo, hi, acc[r][cp]);
                float2 o;
                o.x = fmaxf(lo + bv, 0.0f);
                o.y = fmaxf(hi + bv, 0.0f);
                *(float2*)&g_H[(size_t)m * NTOT + ncolb + cp * 2] = o;
            }
        }
    } else {
        int b = n0 >> 14;
        int t0 = ncolb & (T_LEN - 1);
#pragma unroll
        for (int r = 0; r < 8; r++) {
            int m = mbase + my * 8 + r;
            float bv = bias[m];
#pragma unroll
            for (int cp = 0; cp < 4; cp++) {
                float lo, hi;
                UNPACK2(lo, hi, acc[r][cp]);
                float2 o; o.x = lo + bv; o.y = hi + bv;
                *(float2*)&dout[((size_t)b * NQ + m) * T_LEN + t0 + cp * 2] = o;
            }
        }
    }
}

// ---------------- launch ----------------
extern "C" void kernel_launch(void* const* d_in, const int* in_sizes, int n_in,
                              void* d_out, int out_size) {
    const float* wave  = (const float*)d_in[0];
    const float* W_in  = (const float*)d_in[1];
    const float* b_in  = (const float*)d_in[2];
    const float* Wf    = (const float*)d_in[3];
    const float* bf    = (const float*)d_in[4];
    const float* Wg    = (const float*)d_in[5];
    const float* bg    = (const float*)d_in[6];
    const float* Wres  = (const float*)d_in[7];
    const float* bres  = (const float*)d_in[8];
    const float* Wskip = (const float*)d_in[9];
    const float* bskip = (const float*)d_in[10];
    const float* W1    = (const float*)d_in[11];
    const float* b1    = (const float*)d_in[12];
    const float* W2    = (const float*)d_in[13];
    const float* b2    = (const float*)d_in[14];
    float* out = (float*)d_out;

    pack_fg_kernel<<<(NBLK * 240 * 256 + 255) / 256, 256>>>(Wf, bf, Wg, bg);
    pack_rs_kernel<<<(NBLK * 128 * 384 + 255) / 256, 256>>>(Wres, bres, Wskip, bskip);
    pack_heads_kernel<<<(256 * 256 + 255) / 256, 256>>>(W1, W2);
    init_kernel<<<(360 * NTOT) / 256, 256>>>(wave, W_in, b_in);

    static const int dil[NBLK] = {1, 2, 4, 8, 16, 32, 64, 128,
                                  1, 2, 4, 8, 16, 32, 64, 128};

    dim3 gFG(NTOT / 128, 2);
    dim3 gRS(NTOT / 128, 3);
    dim3 gH (NTOT / 128, 2);

    for (int i = 0; i < NBLK; i++) {
        int d = dil[i];
        if (d == 1)
            gemm_kernel<240, 240, 0, 0, 256, 1><<<gFG, 256>>>(i, d, nullptr, nullptr);
        else if (d == 2)
            gemm_kernel<240, 240, 0, 0, 256, 2><<<gFG, 256>>>(i, d, nullptr, nullptr);
        else
            gemm_kernel<240, 240, 0, 0, 256, 4><<<gFG, 256>>>(i, d, nullptr, nullptr);
        gemm_kernel<128, 120, 1, 1, 384, 4><<<gRS, 256>>>(i, 0, nullptr, nullptr);
    }
    gemm_kernel<240, 240, 2, 2, 256, 4><<<gH, 256>>>(0, 0, b1, nullptr);
    gemm_kernel<256, 256, 1, 3, 256, 4><<<gH, 256>>>(0, 0, b2, out);
}